// round 1
// baseline (speedup 1.0000x reference)
#include <cuda_runtime.h>
#include <cstdint>

// ---------------------------------------------------------------------------
// FeatureAlign: 3 pyramid levels, each through 2 stacked deformable conv1d
// layers.  Per layer:
//   off = conv1d_same(x, ow) + ob + off_prev          (B,3,T)
//   x   = relu( deform_conv1d(x, off, w) + b ) * mask (B,512,T)
// Deform conv is im2col (linear interp, zero pad) + GEMM:
//   Y[b*T+t, o] = sum_{k,c} S[b*T+t, k*512+c] * W2[k*512+c, o]
// Activations kept in (B,T,C) layout so GEMM output == next layer input.
// ---------------------------------------------------------------------------

#define BSZ   8
#define CCH   512
#define KT    3
#define MAXT  2048
#define KRED  (KT*CCH)   // 1536

// scratch (device globals: no runtime allocation allowed)
__device__ float g_xT_a[BSZ*MAXT*CCH];        // 33.5 MB
__device__ float g_xT_b[BSZ*MAXT*CCH];        // 33.5 MB
__device__ float g_S[BSZ*MAXT*KRED];          // 100.7 MB
__device__ float g_off_a[BSZ*KT*MAXT];
__device__ float g_off_b[BSZ*KT*MAXT];
__device__ float g_W2[2*KRED*CCH];            // 6.3 MB

// ---------------------------------------------------------------------------
// generic batched transpose: in (B, R, S) -> out (B, S, R)
// grid (S/32, R/32, B), block (32, 8)
__global__ void transpose_kernel(const float* __restrict__ in,
                                 float* __restrict__ out, int R, int S) {
    __shared__ float tile[32][33];
    int b  = blockIdx.z;
    int s0 = blockIdx.x * 32, r0 = blockIdx.y * 32;
    const float* inb  = in  + (size_t)b * R * S;
    float*       outb = out + (size_t)b * R * S;
    #pragma unroll
    for (int i = threadIdx.y; i < 32; i += 8)
        tile[i][threadIdx.x] = inb[(size_t)(r0 + i) * S + s0 + threadIdx.x];
    __syncthreads();
    #pragma unroll
    for (int i = threadIdx.y; i < 32; i += 8)
        outb[(size_t)(s0 + i) * R + r0 + threadIdx.x] = tile[threadIdx.x][i];
}

// ---------------------------------------------------------------------------
// W2[l][k*C+c][o] = w_l[(o*C + c)*K + k]
__global__ void prep_w2_kernel(const float* __restrict__ w0,
                               const float* __restrict__ w1,
                               float* __restrict__ W2) {
    int idx = blockIdx.x * blockDim.x + threadIdx.x;
    if (idx >= 2 * KRED * CCH) return;
    int l   = idx / (KRED * CCH);
    int rem = idx % (KRED * CCH);
    int r = rem / CCH, o = rem % CCH;
    int k = r / CCH,   c = r % CCH;
    const float* w = l ? w1 : w0;
    W2[idx] = w[(o * CCH + c) * KT + k];
}

// ---------------------------------------------------------------------------
// offset conv: one warp per (b,t).  xT is (B,T,C).
// off_out[b,k,t] = sum_{c,j} ow[k,c,j]*xpad[b,c,t+j-1] + ob[k] + off_in[b,k,t]
__global__ void offset_kernel(const float* __restrict__ xT,
                              const float* __restrict__ off_in,
                              const float* __restrict__ ow,
                              const float* __restrict__ ob,
                              float* __restrict__ off_out, int T) {
    __shared__ float ow_sh[KT * CCH * KT];   // 4608 floats = 18 KB
    for (int i = threadIdx.x; i < KT * CCH * KT; i += blockDim.x)
        ow_sh[i] = ow[i];
    __syncthreads();

    int warp = threadIdx.x >> 5, lane = threadIdx.x & 31;
    int gw = blockIdx.x * (blockDim.x >> 5) + warp;   // (b,t) index
    int b = gw / T, t = gw % T;

    const float* xb = xT + (size_t)b * T * CCH;
    const float* x0 = xb + (size_t)t * CCH;
    const float* xm = (t > 0)     ? xb + (size_t)(t - 1) * CCH : nullptr;
    const float* xp = (t < T - 1) ? xb + (size_t)(t + 1) * CCH : nullptr;

    float acc0 = 0.f, acc1 = 0.f, acc2 = 0.f;
    for (int c = lane; c < CCH; c += 32) {
        float vm = xm ? xm[c] : 0.f;
        float v0 = x0[c];
        float vp = xp ? xp[c] : 0.f;
        const float* o0 = &ow_sh[(0 * CCH + c) * KT];
        const float* o1 = &ow_sh[(1 * CCH + c) * KT];
        const float* o2 = &ow_sh[(2 * CCH + c) * KT];
        acc0 += o0[0] * vm + o0[1] * v0 + o0[2] * vp;
        acc1 += o1[0] * vm + o1[1] * v0 + o1[2] * vp;
        acc2 += o2[0] * vm + o2[1] * v0 + o2[2] * vp;
    }
    #pragma unroll
    for (int s = 16; s; s >>= 1) {
        acc0 += __shfl_down_sync(0xffffffffu, acc0, s);
        acc1 += __shfl_down_sync(0xffffffffu, acc1, s);
        acc2 += __shfl_down_sync(0xffffffffu, acc2, s);
    }
    if (lane == 0) {
        size_t base = (size_t)b * KT * T + t;
        off_out[base + 0 * T] = acc0 + ob[0] + off_in[base + 0 * T];
        off_out[base + 1 * T] = acc1 + ob[1] + off_in[base + 1 * T];
        off_out[base + 2 * T] = acc2 + ob[2] + off_in[base + 2 * T];
    }
}

// ---------------------------------------------------------------------------
// im2col with linear interpolation + zero padding.
// grid (B*T, 3), block 128 (one float4 per thread covers 512 channels)
__global__ void im2col_kernel(const float* __restrict__ xT,
                              const float* __restrict__ off,
                              float* __restrict__ S, int T) {
    int bt = blockIdx.x;
    int k  = blockIdx.y;
    int b = bt / T, t = bt % T;

    float o   = off[((size_t)b * KT + k) * T + t];
    float pos = (float)t + (float)(k - 1) + o;
    float p0  = floorf(pos);
    float f   = pos - p0;
    int   i0  = (int)p0;
    int   i1  = i0 + 1;
    float v0  = (i0 >= 0 && i0 < T) ? 1.f : 0.f;
    float v1  = (i1 >= 0 && i1 < T) ? 1.f : 0.f;
    int i0c = min(max(i0, 0), T - 1);
    int i1c = min(max(i1, 0), T - 1);

    float w0 = v0 * (1.f - f), w1 = v1 * f;
    const float4* r0 = (const float4*)(xT + ((size_t)b * T + i0c) * CCH);
    const float4* r1 = (const float4*)(xT + ((size_t)b * T + i1c) * CCH);
    float4*       dst = (float4*)(S + (size_t)bt * KRED + (size_t)k * CCH);

    int i = threadIdx.x;                  // 0..127
    float4 a = r0[i], c = r1[i];
    dst[i] = make_float4(w0 * a.x + w1 * c.x, w0 * a.y + w1 * c.y,
                         w0 * a.z + w1 * c.z, w0 * a.w + w1 * c.w);
}

// ---------------------------------------------------------------------------
// SGEMM  C[M,512] = A[M,1536] * Bw[1536,512], epilogue: +bias, relu, *mask
// BM=BN=128, BK=8, 256 threads, 8x8 per thread.
__global__ __launch_bounds__(256)
void sgemm_kernel(const float* __restrict__ A, const float* __restrict__ Bw,
                  const float* __restrict__ bias, const float* __restrict__ mask,
                  float* __restrict__ C, int M) {
    const int N = CCH, Kred = KRED;
    __shared__ float As[8][128];
    __shared__ float Bs[8][128];

    int tid = threadIdx.x;
    int br = blockIdx.y, bc = blockIdx.x;

    const float* Ab = A  + (size_t)br * 128 * Kred;
    const float* Bb = Bw + (size_t)bc * 128;

    int arow = tid >> 1,  acol = (tid & 1) * 4;
    int brow = tid >> 5,  bcol = (tid & 31) * 4;
    int trow = (tid >> 4) * 8, tcol = (tid & 15) * 8;

    float acc[8][8];
    #pragma unroll
    for (int i = 0; i < 8; i++)
        #pragma unroll
        for (int j = 0; j < 8; j++) acc[i][j] = 0.f;

    for (int k0 = 0; k0 < Kred; k0 += 8) {
        float4 av = *(const float4*)(Ab + (size_t)arow * Kred + k0 + acol);
        As[acol + 0][arow] = av.x;
        As[acol + 1][arow] = av.y;
        As[acol + 2][arow] = av.z;
        As[acol + 3][arow] = av.w;
        *(float4*)(&Bs[brow][bcol]) =
            *(const float4*)(Bb + (size_t)(k0 + brow) * N + bcol);
        __syncthreads();
        #pragma unroll
        for (int kk = 0; kk < 8; kk++) {
            float ra[8], rb[8];
            *(float4*)(ra)     = *(const float4*)(&As[kk][trow]);
            *(float4*)(ra + 4) = *(const float4*)(&As[kk][trow + 4]);
            *(float4*)(rb)     = *(const float4*)(&Bs[kk][tcol]);
            *(float4*)(rb + 4) = *(const float4*)(&Bs[kk][tcol + 4]);
            #pragma unroll
            for (int i = 0; i < 8; i++)
                #pragma unroll
                for (int j = 0; j < 8; j++)
                    acc[i][j] += ra[i] * rb[j];
        }
        __syncthreads();
    }

    float bv[8];
    #pragma unroll
    for (int j = 0; j < 8; j++) bv[j] = bias[bc * 128 + tcol + j];

    #pragma unroll
    for (int i = 0; i < 8; i++) {
        int m = br * 128 + trow + i;            // m = b*T + t; mask is (B,1,T)
        float mv = mask[m];
        float out[8];
        #pragma unroll
        for (int j = 0; j < 8; j++)
            out[j] = fmaxf(acc[i][j] + bv[j], 0.f) * mv;
        float* cp = C + (size_t)m * N + bc * 128 + tcol;
        *(float4*)(cp)     = *(float4*)(out);
        *(float4*)(cp + 4) = *(float4*)(out + 4);
    }
}

// ---------------------------------------------------------------------------
__global__ void mask_kernel(const float* __restrict__ in,
                            float* __restrict__ out, int n) {
    int i = blockIdx.x * blockDim.x + threadIdx.x;
    if (i < n) out[i] = (in[i] != 0.f) ? 1.0f : 0.0f;
}

// ---------------------------------------------------------------------------
extern "C" void kernel_launch(void* const* d_in, const int* in_sizes, int n_in,
                              void* d_out, int out_size) {
    // classify inputs by element count (robust to metadata ordering;
    // duplicated sizes resolved by first-occurrence order = layer order)
    const float *feats[3] = {}, *masks[3] = {}, *offs[3] = {};
    const float *w[2] = {}, *bias[2] = {}, *ow[2] = {}, *ob[2] = {};
    int wi = 0, bi = 0, owi = 0, obi = 0;
    for (int i = 0; i < n_in; i++) {
        const float* p = (const float*)d_in[i];
        switch (in_sizes[i]) {
            case 8 * 512 * 2048: feats[0] = p; break;
            case 8 * 512 * 1024: feats[1] = p; break;
            case 8 * 512 * 512:  feats[2] = p; break;
            case 8 * 2048:       masks[0] = p; break;
            case 8 * 1024:       masks[1] = p; break;
            case 8 * 512:        masks[2] = p; break;
            case 8 * 3 * 2048:   offs[0]  = p; break;
            case 8 * 3 * 1024:   offs[1]  = p; break;
            case 8 * 3 * 512:    offs[2]  = p; break;
            case 512 * 512 * 3:  if (wi  < 2) w[wi++]   = p; break;
            case 512:            if (bi  < 2) bias[bi++] = p; break;
            case 3 * 512 * 3:    if (owi < 2) ow[owi++] = p; break;
            case 3:              if (obi < 2) ob[obi++] = p; break;
            default: break;
        }
    }

    float *xTa, *xTb, *Sb, *offa, *offb, *W2;
    cudaGetSymbolAddress((void**)&xTa, g_xT_a);
    cudaGetSymbolAddress((void**)&xTb, g_xT_b);
    cudaGetSymbolAddress((void**)&Sb,  g_S);
    cudaGetSymbolAddress((void**)&offa, g_off_a);
    cudaGetSymbolAddress((void**)&offb, g_off_b);
    cudaGetSymbolAddress((void**)&W2,  g_W2);

    float* out = (float*)d_out;

    // weight repack (cheap, re-run every replay for determinism)
    {
        int total = 2 * KRED * CCH;
        prep_w2_kernel<<<(total + 255) / 256, 256>>>(w[0], w[1], W2);
    }

    const int Ts[3] = {2048, 1024, 512};
    size_t outBase[3] = {0,
                         (size_t)BSZ * CCH * 2048,
                         (size_t)BSZ * CCH * (2048 + 1024)};
    size_t maskBase0 = (size_t)BSZ * CCH * (2048 + 1024 + 512);
    size_t maskBase[3] = {maskBase0,
                          maskBase0 + (size_t)BSZ * 2048,
                          maskBase0 + (size_t)BSZ * (2048 + 1024)};

    for (int lv = 0; lv < 3; lv++) {
        int T = Ts[lv];
        int M = BSZ * T;

        // (B,C,T) -> (B,T,C)
        transpose_kernel<<<dim3(T / 32, CCH / 32, BSZ), dim3(32, 8)>>>(
            feats[lv], xTa, CCH, T);

        // ---- layer 0 ----
        offset_kernel<<<M / 8, 256>>>(xTa, offs[lv], ow[0], ob[0], offb, T);
        im2col_kernel<<<dim3(M, KT), 128>>>(xTa, offb, Sb, T);
        sgemm_kernel<<<dim3(CCH / 128, M / 128), 256>>>(
            Sb, W2, bias[0], masks[lv], xTb, M);

        // ---- layer 1 ----
        offset_kernel<<<M / 8, 256>>>(xTb, offb, ow[1], ob[1], offa, T);
        im2col_kernel<<<dim3(M, KT), 128>>>(xTb, offa, Sb, T);
        sgemm_kernel<<<dim3(CCH / 128, M / 128), 256>>>(
            Sb, W2 + (size_t)KRED * CCH, bias[1], masks[lv], xTa, M);

        // (B,T,C) -> (B,C,T) into output slot
        transpose_kernel<<<dim3(CCH / 32, T / 32, BSZ), dim3(32, 8)>>>(
            xTa, out + outBase[lv], T, CCH);

        // bool mask output (as 1.0 / 0.0 in output dtype)
        int nm = BSZ * T;
        mask_kernel<<<(nm + 255) / 256, 256>>>(masks[lv], out + maskBase[lv], nm);
    }
}

// round 2
// speedup vs baseline: 1.0133x; 1.0133x over previous
#include <cuda_runtime.h>
#include <cstdint>

// ---------------------------------------------------------------------------
// FeatureAlign: 3 pyramid levels, each through 2 stacked deformable conv1d
// layers.  Per layer:
//   off = conv1d_same(x, ow) + ob + off_prev          (B,3,T)
//   x   = relu( deform_conv1d(x, off, w) + b ) * mask (B,512,T)
// Deform conv is im2col (linear interp, zero pad) + GEMM:
//   Y[b*T+t, o] = sum_{k,c} S[b*T+t, k*512+c] * W2[k*512+c, o]
// Activations kept in (B,T,C) layout so GEMM output == next layer input.
// ---------------------------------------------------------------------------

#define BSZ   8
#define CCH   512
#define KT    3
#define MAXT  2048
#define KRED  (KT*CCH)   // 1536

// scratch (device globals: no runtime allocation allowed)
__device__ float g_xT_a[BSZ*MAXT*CCH];        // 33.5 MB
__device__ float g_xT_b[BSZ*MAXT*CCH];        // 33.5 MB
__device__ float g_S[BSZ*MAXT*KRED];          // 100.7 MB
__device__ float g_off_a[BSZ*KT*MAXT];
__device__ float g_off_b[BSZ*KT*MAXT];
__device__ float g_W2[2*KRED*CCH];            // 6.3 MB

// ---------------------------------------------------------------------------
// generic batched transpose: in (B, R, S) -> out (B, S, R)
// grid (S/32, R/32, B), block (32, 8)
__global__ void transpose_kernel(const float* __restrict__ in,
                                 float* __restrict__ out, int R, int S) {
    __shared__ float tile[32][33];
    int b  = blockIdx.z;
    int s0 = blockIdx.x * 32, r0 = blockIdx.y * 32;
    const float* inb  = in  + (size_t)b * R * S;
    float*       outb = out + (size_t)b * R * S;
    #pragma unroll
    for (int i = threadIdx.y; i < 32; i += 8)
        tile[i][threadIdx.x] = inb[(size_t)(r0 + i) * S + s0 + threadIdx.x];
    __syncthreads();
    #pragma unroll
    for (int i = threadIdx.y; i < 32; i += 8)
        outb[(size_t)(s0 + i) * R + r0 + threadIdx.x] = tile[threadIdx.x][i];
}

// ---------------------------------------------------------------------------
// W2[l][k*C+c][o] = w_l[(o*C + c)*K + k]
__global__ void prep_w2_kernel(const float* __restrict__ w0,
                               const float* __restrict__ w1,
                               float* __restrict__ W2) {
    int idx = blockIdx.x * blockDim.x + threadIdx.x;
    if (idx >= 2 * KRED * CCH) return;
    int l   = idx / (KRED * CCH);
    int rem = idx % (KRED * CCH);
    int r = rem / CCH, o = rem % CCH;
    int k = r / CCH,   c = r % CCH;
    const float* w = l ? w1 : w0;
    W2[idx] = w[(o * CCH + c) * KT + k];
}

// ---------------------------------------------------------------------------
// offset conv: one warp per (b,t).  xT is (B,T,C).
// off_out[b,k,t] = sum_{c,j} ow[k,c,j]*xpad[b,c,t+j-1] + ob[k] + off_in[b,k,t]
__global__ void offset_kernel(const float* __restrict__ xT,
                              const float* __restrict__ off_in,
                              const float* __restrict__ ow,
                              const float* __restrict__ ob,
                              float* __restrict__ off_out, int T) {
    __shared__ float ow_sh[KT * CCH * KT];   // 4608 floats = 18 KB
    for (int i = threadIdx.x; i < KT * CCH * KT; i += blockDim.x)
        ow_sh[i] = ow[i];
    __syncthreads();

    int warp = threadIdx.x >> 5, lane = threadIdx.x & 31;
    int gw = blockIdx.x * (blockDim.x >> 5) + warp;   // (b,t) index
    int b = gw / T, t = gw % T;

    const float* xb = xT + (size_t)b * T * CCH;
    const float* x0 = xb + (size_t)t * CCH;
    const float* xm = (t > 0)     ? xb + (size_t)(t - 1) * CCH : nullptr;
    const float* xp = (t < T - 1) ? xb + (size_t)(t + 1) * CCH : nullptr;

    float acc0 = 0.f, acc1 = 0.f, acc2 = 0.f;
    for (int c = lane; c < CCH; c += 32) {
        float vm = xm ? xm[c] : 0.f;
        float v0 = x0[c];
        float vp = xp ? xp[c] : 0.f;
        const float* o0 = &ow_sh[(0 * CCH + c) * KT];
        const float* o1 = &ow_sh[(1 * CCH + c) * KT];
        const float* o2 = &ow_sh[(2 * CCH + c) * KT];
        acc0 += o0[0] * vm + o0[1] * v0 + o0[2] * vp;
        acc1 += o1[0] * vm + o1[1] * v0 + o1[2] * vp;
        acc2 += o2[0] * vm + o2[1] * v0 + o2[2] * vp;
    }
    #pragma unroll
    for (int s = 16; s; s >>= 1) {
        acc0 += __shfl_down_sync(0xffffffffu, acc0, s);
        acc1 += __shfl_down_sync(0xffffffffu, acc1, s);
        acc2 += __shfl_down_sync(0xffffffffu, acc2, s);
    }
    if (lane == 0) {
        size_t base = (size_t)b * KT * T + t;
        off_out[base + 0 * T] = acc0 + ob[0] + off_in[base + 0 * T];
        off_out[base + 1 * T] = acc1 + ob[1] + off_in[base + 1 * T];
        off_out[base + 2 * T] = acc2 + ob[2] + off_in[base + 2 * T];
    }
}

// ---------------------------------------------------------------------------
// im2col with linear interpolation + zero padding.
// grid (B*T, 3), block 128 (one float4 per thread covers 512 channels)
__global__ void im2col_kernel(const float* __restrict__ xT,
                              const float* __restrict__ off,
                              float* __restrict__ S, int T) {
    int bt = blockIdx.x;
    int k  = blockIdx.y;
    int b = bt / T, t = bt % T;

    float o   = off[((size_t)b * KT + k) * T + t];
    float pos = (float)t + (float)(k - 1) + o;
    float p0  = floorf(pos);
    float f   = pos - p0;
    int   i0  = (int)p0;
    int   i1  = i0 + 1;
    float v0  = (i0 >= 0 && i0 < T) ? 1.f : 0.f;
    float v1  = (i1 >= 0 && i1 < T) ? 1.f : 0.f;
    int i0c = min(max(i0, 0), T - 1);
    int i1c = min(max(i1, 0), T - 1);

    float w0 = v0 * (1.f - f), w1 = v1 * f;
    const float4* r0 = (const float4*)(xT + ((size_t)b * T + i0c) * CCH);
    const float4* r1 = (const float4*)(xT + ((size_t)b * T + i1c) * CCH);
    float4*       dst = (float4*)(S + (size_t)bt * KRED + (size_t)k * CCH);

    int i = threadIdx.x;                  // 0..127
    float4 a = r0[i], c = r1[i];
    dst[i] = make_float4(w0 * a.x + w1 * c.x, w0 * a.y + w1 * c.y,
                         w0 * a.z + w1 * c.z, w0 * a.w + w1 * c.w);
}

// ---------------------------------------------------------------------------
// SGEMM  C[M,512] = A[M,1536] * Bw[1536,512], epilogue: +bias, relu, *mask
// BM=BN=128, BK=8, 256 threads, 8x8 per thread.
__global__ __launch_bounds__(256)
void sgemm_kernel(const float* __restrict__ A, const float* __restrict__ Bw,
                  const float* __restrict__ bias, const float* __restrict__ mask,
                  float* __restrict__ C, int M) {
    const int N = CCH, Kred = KRED;
    __shared__ float As[8][128];
    __shared__ float Bs[8][128];

    int tid = threadIdx.x;
    int br = blockIdx.y, bc = blockIdx.x;

    const float* Ab = A  + (size_t)br * 128 * Kred;
    const float* Bb = Bw + (size_t)bc * 128;

    int arow = tid >> 1,  acol = (tid & 1) * 4;
    int brow = tid >> 5,  bcol = (tid & 31) * 4;
    int trow = (tid >> 4) * 8, tcol = (tid & 15) * 8;

    float acc[8][8];
    #pragma unroll
    for (int i = 0; i < 8; i++)
        #pragma unroll
        for (int j = 0; j < 8; j++) acc[i][j] = 0.f;

    for (int k0 = 0; k0 < Kred; k0 += 8) {
        float4 av = *(const float4*)(Ab + (size_t)arow * Kred + k0 + acol);
        As[acol + 0][arow] = av.x;
        As[acol + 1][arow] = av.y;
        As[acol + 2][arow] = av.z;
        As[acol + 3][arow] = av.w;
        *(float4*)(&Bs[brow][bcol]) =
            *(const float4*)(Bb + (size_t)(k0 + brow) * N + bcol);
        __syncthreads();
        #pragma unroll
        for (int kk = 0; kk < 8; kk++) {
            float ra[8], rb[8];
            *(float4*)(ra)     = *(const float4*)(&As[kk][trow]);
            *(float4*)(ra + 4) = *(const float4*)(&As[kk][trow + 4]);
            *(float4*)(rb)     = *(const float4*)(&Bs[kk][tcol]);
            *(float4*)(rb + 4) = *(const float4*)(&Bs[kk][tcol + 4]);
            #pragma unroll
            for (int i = 0; i < 8; i++)
                #pragma unroll
                for (int j = 0; j < 8; j++)
                    acc[i][j] += ra[i] * rb[j];
        }
        __syncthreads();
    }

    float bv[8];
    #pragma unroll
    for (int j = 0; j < 8; j++) bv[j] = bias[bc * 128 + tcol + j];

    #pragma unroll
    for (int i = 0; i < 8; i++) {
        int m = br * 128 + trow + i;            // m = b*T + t; mask is (B,1,T)
        float mv = mask[m];
        float out[8];
        #pragma unroll
        for (int j = 0; j < 8; j++)
            out[j] = fmaxf(acc[i][j] + bv[j], 0.f) * mv;
        float* cp = C + (size_t)m * N + bc * 128 + tcol;
        *(float4*)(cp)     = *(float4*)(out);
        *(float4*)(cp + 4) = *(float4*)(out + 4);
    }
}

// ---------------------------------------------------------------------------
__global__ void mask_kernel(const float* __restrict__ in,
                            float* __restrict__ out, int n) {
    int i = blockIdx.x * blockDim.x + threadIdx.x;
    if (i < n) out[i] = (in[i] != 0.f) ? 1.0f : 0.0f;
}

// ---------------------------------------------------------------------------
extern "C" void kernel_launch(void* const* d_in, const int* in_sizes, int n_in,
                              void* d_out, int out_size) {
    // classify inputs by element count (robust to metadata ordering;
    // duplicated sizes resolved by first-occurrence order = layer order)
    const float *feats[3] = {}, *masks[3] = {}, *offs[3] = {};
    const float *w[2] = {}, *bias[2] = {}, *ow[2] = {}, *ob[2] = {};
    int wi = 0, bi = 0, owi = 0, obi = 0;
    for (int i = 0; i < n_in; i++) {
        const float* p = (const float*)d_in[i];
        switch (in_sizes[i]) {
            case 8 * 512 * 2048: feats[0] = p; break;
            case 8 * 512 * 1024: feats[1] = p; break;
            case 8 * 512 * 512:  feats[2] = p; break;
            case 8 * 2048:       masks[0] = p; break;
            case 8 * 1024:       masks[1] = p; break;
            case 8 * 512:        masks[2] = p; break;
            case 8 * 3 * 2048:   offs[0]  = p; break;
            case 8 * 3 * 1024:   offs[1]  = p; break;
            case 8 * 3 * 512:    offs[2]  = p; break;
            case 512 * 512 * 3:  if (wi  < 2) w[wi++]   = p; break;
            case 512:            if (bi  < 2) bias[bi++] = p; break;
            case 3 * 512 * 3:    if (owi < 2) ow[owi++] = p; break;
            case 3:              if (obi < 2) ob[obi++] = p; break;
            default: break;
        }
    }

    float *xTa, *xTb, *Sb, *offa, *offb, *W2;
    cudaGetSymbolAddress((void**)&xTa, g_xT_a);
    cudaGetSymbolAddress((void**)&xTb, g_xT_b);
    cudaGetSymbolAddress((void**)&Sb,  g_S);
    cudaGetSymbolAddress((void**)&offa, g_off_a);
    cudaGetSymbolAddress((void**)&offb, g_off_b);
    cudaGetSymbolAddress((void**)&W2,  g_W2);

    float* out = (float*)d_out;

    // weight repack (cheap, re-run every replay for determinism)
    {
        int total = 2 * KRED * CCH;
        prep_w2_kernel<<<(total + 255) / 256, 256>>>(w[0], w[1], W2);
    }

    const int Ts[3] = {2048, 1024, 512};
    size_t outBase[3] = {0,
                         (size_t)BSZ * CCH * 2048,
                         (size_t)BSZ * CCH * (2048 + 1024)};
    size_t maskBase0 = (size_t)BSZ * CCH * (2048 + 1024 + 512);
    size_t maskBase[3] = {maskBase0,
                          maskBase0 + (size_t)BSZ * 2048,
                          maskBase0 + (size_t)BSZ * (2048 + 1024)};

    for (int lv = 0; lv < 3; lv++) {
        int T = Ts[lv];
        int M = BSZ * T;

        // (B,C,T) -> (B,T,C)
        transpose_kernel<<<dim3(T / 32, CCH / 32, BSZ), dim3(32, 8)>>>(
            feats[lv], xTa, CCH, T);

        // ---- layer 0 ----
        offset_kernel<<<M / 8, 256>>>(xTa, offs[lv], ow[0], ob[0], offb, T);
        im2col_kernel<<<dim3(M, KT), 128>>>(xTa, offb, Sb, T);
        sgemm_kernel<<<dim3(CCH / 128, M / 128), 256>>>(
            Sb, W2, bias[0], masks[lv], xTb, M);

        // ---- layer 1 ----
        offset_kernel<<<M / 8, 256>>>(xTb, offb, ow[1], ob[1], offa, T);
        im2col_kernel<<<dim3(M, KT), 128>>>(xTb, offa, Sb, T);
        sgemm_kernel<<<dim3(CCH / 128, M / 128), 256>>>(
            Sb, W2 + (size_t)KRED * CCH, bias[1], masks[lv], xTa, M);

        // (B,T,C) -> (B,C,T) into output slot
        transpose_kernel<<<dim3(CCH / 32, T / 32, BSZ), dim3(32, 8)>>>(
            xTa, out + outBase[lv], T, CCH);

        // bool mask output (as 1.0 / 0.0 in output dtype)
        int nm = BSZ * T;
        mask_kernel<<<(nm + 255) / 256, 256>>>(masks[lv], out + maskBase[lv], nm);
    }
}

// round 4
// speedup vs baseline: 2.5490x; 2.5156x over previous
#include <cuda_runtime.h>
#include <cuda_bf16.h>
#include <cstdint>

// ---------------------------------------------------------------------------
// FeatureAlign via mma.sync bf16 (HMMA) with fp32->bf16 hi/lo splitting.
//   Y = relu( A(fp32 gathered) @ W(fp32) + b ) * mask
//   A@W ~= Ah@Wh + Ah@Wl + Al@Wh   (fp32 accum)
// All 3 pyramid levels concatenated into 28672 rows; one GEMM per layer.
// ---------------------------------------------------------------------------

#define BSZ 8
#define CCH 512
#define KT  3
#define ROWS_TOTAL 28672
#define LV0 16384
#define LV01 24576
#define KRED 1536

// GEMM tiling
#define BMM 128
#define BNN 128
#define BKK 32
#define AST 40                      // A smem row stride (bf16 elems): 32 + 8 pad
#define BST 136                     // B smem row stride: 128 + 8 pad
#define A_ELE (BMM*AST)             // 5120
#define B_ELE (BKK*BST)             // 4352
#define STG_BYTES ((2*A_ELE + 2*B_ELE)*2)   // 37888 B per stage
#define NSTAGE 3
#define GEMM_SMEM (NSTAGE*STG_BYTES)        // 113664 B
#define KITERS (KRED/BKK)           // 48

// scratch (device globals; no runtime allocation allowed)
__device__ float g_x[ROWS_TOTAL * CCH];
__device__ float g_y[ROWS_TOTAL * CCH];
__device__ float g_offa[ROWS_TOTAL * 4];
__device__ float g_offb[ROWS_TOTAL * 4];
__device__ float g_mrow[ROWS_TOTAL];
__device__ __nv_bfloat16 g_Ah[(size_t)ROWS_TOTAL * KRED];
__device__ __nv_bfloat16 g_Al[(size_t)ROWS_TOTAL * KRED];
__device__ __nv_bfloat16 g_Wh[2 * KRED * CCH];
__device__ __nv_bfloat16 g_Wl[2 * KRED * CCH];

// ---------------------------------------------------------------------------
__device__ __forceinline__ uint32_t smem_u32(const void* p) {
    return (uint32_t)__cvta_generic_to_shared(p);
}
#define CP16(sa, gp) \
    asm volatile("cp.async.cg.shared.global [%0], [%1], 16;" :: "r"(sa), "l"(gp))
#define CP_COMMIT() asm volatile("cp.async.commit_group;")
#define CP_WAIT1()  asm volatile("cp.async.wait_group 1;")

__device__ __forceinline__ void ldsm_x4(uint32_t* r, uint32_t a) {
    asm volatile("ldmatrix.sync.aligned.m8n8.x4.shared.b16 {%0,%1,%2,%3}, [%4];"
                 : "=r"(r[0]), "=r"(r[1]), "=r"(r[2]), "=r"(r[3]) : "r"(a));
}
__device__ __forceinline__ void ldsm_x4_t(uint32_t* r, uint32_t a) {
    asm volatile("ldmatrix.sync.aligned.m8n8.x4.trans.shared.b16 {%0,%1,%2,%3}, [%4];"
                 : "=r"(r[0]), "=r"(r[1]), "=r"(r[2]), "=r"(r[3]) : "r"(a));
}
__device__ __forceinline__ void mma16816(float* d, const uint32_t* a,
                                         const uint32_t* b) {
    asm volatile("mma.sync.aligned.m16n8k16.row.col.f32.bf16.bf16.f32 "
                 "{%0,%1,%2,%3}, {%4,%5,%6,%7}, {%8,%9}, {%0,%1,%2,%3};"
                 : "+f"(d[0]), "+f"(d[1]), "+f"(d[2]), "+f"(d[3])
                 : "r"(a[0]), "r"(a[1]), "r"(a[2]), "r"(a[3]), "r"(b[0]), "r"(b[1]));
}

// ---------------------------------------------------------------------------
// batched transpose: in (B, R, S) -> out (B, S, R)
__global__ void transpose_kernel(const float* __restrict__ in,
                                 float* __restrict__ out, int R, int S) {
    __shared__ float tile[32][33];
    int b = blockIdx.z, s0 = blockIdx.x * 32, r0 = blockIdx.y * 32;
    const float* inb = in + (size_t)b * R * S;
    float* outb = out + (size_t)b * R * S;
    #pragma unroll
    for (int i = threadIdx.y; i < 32; i += 8)
        tile[i][threadIdx.x] = inb[(size_t)(r0 + i) * S + s0 + threadIdx.x];
    __syncthreads();
    #pragma unroll
    for (int i = threadIdx.y; i < 32; i += 8)
        outb[(size_t)(s0 + i) * R + r0 + threadIdx.x] = tile[threadIdx.x][i];
}

// ---------------------------------------------------------------------------
// Wh/Wl[l][k][n], k = ktap*512 + c ; from w[(n*512 + c)*3 + ktap]
__global__ void prep_wsplit_kernel(const float* __restrict__ w0,
                                   const float* __restrict__ w1,
                                   __nv_bfloat16* __restrict__ Wh,
                                   __nv_bfloat16* __restrict__ Wl) {
    int idx = blockIdx.x * blockDim.x + threadIdx.x;
    if (idx >= 2 * KRED * CCH) return;
    int n = idx & 511;
    int k = (idx >> 9) % KRED;
    int l = idx / (KRED * CCH);
    int ktap = k >> 9, c = k & 511;
    const float* w = l ? w1 : w0;
    float val = w[(n * CCH + c) * KT + ktap];
    __nv_bfloat16 hi = __float2bfloat16(val);
    Wh[idx] = hi;
    Wl[idx] = __float2bfloat16(val - __bfloat162float(hi));
}

// ---------------------------------------------------------------------------
__global__ void maskrow_kernel(const float* __restrict__ m0,
                               const float* __restrict__ m1,
                               const float* __restrict__ m2,
                               float* __restrict__ out) {
    int m = blockIdx.x * 256 + threadIdx.x;
    if (m >= ROWS_TOTAL) return;
    out[m] = (m < LV0) ? m0[m] : (m < LV01 ? m1[m - LV0] : m2[m - LV01]);
}
__global__ void maskout_kernel(const float* __restrict__ in,
                               float* __restrict__ out, int n) {
    int i = blockIdx.x * blockDim.x + threadIdx.x;
    if (i < n) out[i] = (in[i] != 0.f) ? 1.0f : 0.0f;
}

// ---------------------------------------------------------------------------
// offset conv: one warp per (b,t). X = this level's rows (row-major C).
template <bool EXT>
__global__ void offset_kernel(const float* __restrict__ X,
                              const float* __restrict__ off_in,
                              const float* __restrict__ ow,
                              const float* __restrict__ ob,
                              float* __restrict__ off_out,  // [m*4+k] absolute
                              int T, int lbase) {
    __shared__ float ow_sh[KT * CCH * KT];
    for (int i = threadIdx.x; i < KT * CCH * KT; i += blockDim.x)
        ow_sh[i] = ow[i];
    __syncthreads();

    int warp = threadIdx.x >> 5, lane = threadIdx.x & 31;
    int rl = blockIdx.x * 8 + warp;
    int b = rl / T, t = rl % T;
    int m = lbase + rl;

    const float* x0 = X + (size_t)rl * CCH;
    const float* xm = (t > 0)     ? x0 - CCH : nullptr;
    const float* xp = (t < T - 1) ? x0 + CCH : nullptr;

    float a0 = 0.f, a1 = 0.f, a2 = 0.f;
    for (int c = lane; c < CCH; c += 32) {
        float vm = xm ? xm[c] : 0.f;
        float v0 = x0[c];
        float vp = xp ? xp[c] : 0.f;
        const float* o0 = &ow_sh[c * KT];
        const float* o1 = &ow_sh[(CCH + c) * KT];
        const float* o2 = &ow_sh[(2 * CCH + c) * KT];
        a0 += o0[0] * vm + o0[1] * v0 + o0[2] * vp;
        a1 += o1[0] * vm + o1[1] * v0 + o1[2] * vp;
        a2 += o2[0] * vm + o2[1] * v0 + o2[2] * vp;
    }
    #pragma unroll
    for (int s = 16; s; s >>= 1) {
        a0 += __shfl_down_sync(0xffffffffu, a0, s);
        a1 += __shfl_down_sync(0xffffffffu, a1, s);
        a2 += __shfl_down_sync(0xffffffffu, a2, s);
    }
    if (lane == 0) {
        float i0, i1, i2;
        if (EXT) {
            i0 = off_in[((size_t)b * KT + 0) * T + t];
            i1 = off_in[((size_t)b * KT + 1) * T + t];
            i2 = off_in[((size_t)b * KT + 2) * T + t];
        } else {
            i0 = off_in[(size_t)m * 4 + 0];
            i1 = off_in[(size_t)m * 4 + 1];
            i2 = off_in[(size_t)m * 4 + 2];
        }
        off_out[(size_t)m * 4 + 0] = a0 + ob[0] + i0;
        off_out[(size_t)m * 4 + 1] = a1 + ob[1] + i1;
        off_out[(size_t)m * 4 + 2] = a2 + ob[2] + i2;
    }
}

// ---------------------------------------------------------------------------
// im2col gather + lerp + bf16 hi/lo split. grid (ROWS_TOTAL, 3), block 128.
__global__ void im2col_split_kernel(const float* __restrict__ X,
                                    const float* __restrict__ OFF,
                                    __nv_bfloat16* __restrict__ Ah,
                                    __nv_bfloat16* __restrict__ Al) {
    int m = blockIdx.x, k = blockIdx.y;
    int lv = (m < LV0) ? 0 : (m < LV01 ? 1 : 2);
    int lbase = (lv == 0) ? 0 : (lv == 1 ? LV0 : LV01);
    int logT = 11 - lv;
    int T = 1 << logT;
    int rl = m - lbase;
    int b = rl >> logT, t = rl & (T - 1);

    float off = OFF[(size_t)m * 4 + k];
    float pos = (float)(t + k - 1) + off;
    float p0f = floorf(pos);
    float f = pos - p0f;
    int i0 = (int)p0f, i1 = i0 + 1;
    float w0 = (i0 >= 0 && i0 < T) ? (1.0f - f) : 0.0f;
    float w1 = (i1 >= 0 && i1 < T) ? f : 0.0f;
    int i0c = min(max(i0, 0), T - 1);
    int i1c = min(max(i1, 0), T - 1);

    size_t rb = (size_t)lbase + ((size_t)b << logT);
    const float4* r0 = (const float4*)(X + (rb + i0c) * CCH);
    const float4* r1 = (const float4*)(X + (rb + i1c) * CCH);

    int i = threadIdx.x;            // 0..127, 4 channels each
    float4 a = r0[i], c = r1[i];
    float e0 = w0 * a.x + w1 * c.x;
    float e1 = w0 * a.y + w1 * c.y;
    float e2 = w0 * a.z + w1 * c.z;
    float e3 = w0 * a.w + w1 * c.w;

    __nv_bfloat162 h01 = __floats2bfloat162_rn(e0, e1);
    __nv_bfloat162 h23 = __floats2bfloat162_rn(e2, e3);
    float2 f01 = __bfloat1622float2(h01);
    float2 f23 = __bfloat1622float2(h23);
    __nv_bfloat162 l01 = __floats2bfloat162_rn(e0 - f01.x, e1 - f01.y);
    __nv_bfloat162 l23 = __floats2bfloat162_rn(e2 - f23.x, e3 - f23.y);

    size_t base = (size_t)m * KRED + (size_t)k * CCH + i * 4;
    uint2 hv, lv2;
    hv.x = *reinterpret_cast<uint32_t*>(&h01);
    hv.y = *reinterpret_cast<uint32_t*>(&h23);
    lv2.x = *reinterpret_cast<uint32_t*>(&l01);
    lv2.y = *reinterpret_cast<uint32_t*>(&l23);
    *(uint2*)(Ah + base) = hv;
    *(uint2*)(Al + base) = lv2;
}

// ---------------------------------------------------------------------------
// GEMM: Y[m,n] = relu( (Ah@Wh + Ah@Wl + Al@Wh)[m,n] + bias[n] ) * maskrow[m]
// grid (4, 224), 256 threads, 3-stage cp.async pipeline.
__global__ __launch_bounds__(256, 1)
void gemm_mma_kernel(const __nv_bfloat16* __restrict__ Ahg,
                     const __nv_bfloat16* __restrict__ Alg,
                     const __nv_bfloat16* __restrict__ Whg,
                     const __nv_bfloat16* __restrict__ Wlg,
                     const float* __restrict__ bias,
                     const float* __restrict__ maskrow,
                     float* __restrict__ Y) {
    extern __shared__ __nv_bfloat16 sm[];
    uint32_t sbase = smem_u32(sm);
    int tid = threadIdx.x, warp = tid >> 5, lane = tid & 31;
    int m0 = blockIdx.y * BMM, n0 = blockIdx.x * BNN;

    const uint32_t offAl = A_ELE * 2;
    const uint32_t offBh = 2 * A_ELE * 2;
    const uint32_t offBl = offBh + B_ELE * 2;

    // cp.async per-thread geometry
    int ar0 = tid >> 2, akc = (tid & 3) * 8;            // A chunk 0: row, kcol
    int br0 = tid >> 4, bnc = (tid & 15) * 8;           // B chunk 0
    const __nv_bfloat16* gAh0 = Ahg + (size_t)(m0 + ar0) * KRED + akc;
    const __nv_bfloat16* gAh1 = Ahg + (size_t)(m0 + ar0 + 64) * KRED + akc;
    const __nv_bfloat16* gAl0 = Alg + (size_t)(m0 + ar0) * KRED + akc;
    const __nv_bfloat16* gAl1 = Alg + (size_t)(m0 + ar0 + 64) * KRED + akc;
    const __nv_bfloat16* gBh0 = Whg + (size_t)br0 * CCH + n0 + bnc;
    const __nv_bfloat16* gBh1 = Whg + (size_t)(br0 + 16) * CCH + n0 + bnc;
    const __nv_bfloat16* gBl0 = Wlg + (size_t)br0 * CCH + n0 + bnc;
    const __nv_bfloat16* gBl1 = Wlg + (size_t)(br0 + 16) * CCH + n0 + bnc;
    uint32_t sA0 = (uint32_t)(ar0 * AST + akc) * 2;
    uint32_t sA1 = (uint32_t)((ar0 + 64) * AST + akc) * 2;
    uint32_t sB0 = (uint32_t)(br0 * BST + bnc) * 2;
    uint32_t sB1 = (uint32_t)((br0 + 16) * BST + bnc) * 2;

    // ldmatrix per-thread offsets (bytes within stage)
    int wm = (warp >> 2) * 64, wn = (warp & 3) * 32;
    int lr = lane & 15, lc = lane >> 4;
    uint32_t a_off[4], b_off[2];
    #pragma unroll
    for (int mt = 0; mt < 4; mt++)
        a_off[mt] = (uint32_t)((wm + mt * 16 + lr) * AST + lc * 8) * 2;
    #pragma unroll
    for (int nt = 0; nt < 2; nt++)
        b_off[nt] = (uint32_t)(lr * BST + wn + nt * 16 + lc * 8) * 2;

    float acc[4][4][4];
    #pragma unroll
    for (int i = 0; i < 4; i++)
        #pragma unroll
        for (int j = 0; j < 4; j++)
            #pragma unroll
            for (int q = 0; q < 4; q++) acc[i][j][q] = 0.f;

    auto load_stage = [&](int st, int k0) {
        uint32_t sb = sbase + (uint32_t)st * STG_BYTES;
        CP16(sb + sA0, gAh0 + k0);
        CP16(sb + sA1, gAh1 + k0);
        CP16(sb + offAl + sA0, gAl0 + k0);
        CP16(sb + offAl + sA1, gAl1 + k0);
        CP16(sb + offBh + sB0, gBh0 + (size_t)k0 * CCH);
        CP16(sb + offBh + sB1, gBh1 + (size_t)k0 * CCH);
        CP16(sb + offBl + sB0, gBl0 + (size_t)k0 * CCH);
        CP16(sb + offBl + sB1, gBl1 + (size_t)k0 * CCH);
    };

    load_stage(0, 0);  CP_COMMIT();
    load_stage(1, BKK); CP_COMMIT();

    for (int it = 0; it < KITERS; it++) {
        CP_WAIT1();
        __syncthreads();
        if (it + 2 < KITERS) load_stage((it + 2) % NSTAGE, (it + 2) * BKK);
        CP_COMMIT();

        uint32_t sb = sbase + (uint32_t)(it % NSTAGE) * STG_BYTES;
        #pragma unroll
        for (int ks = 0; ks < 2; ks++) {
            uint32_t ah[4][4], al[4][4], bh[2][4], bl[2][4];
            #pragma unroll
            for (int mt = 0; mt < 4; mt++) {
                ldsm_x4(ah[mt], sb + a_off[mt] + ks * 32);
                ldsm_x4(al[mt], sb + offAl + a_off[mt] + ks * 32);
            }
            #pragma unroll
            for (int nt = 0; nt < 2; nt++) {
                ldsm_x4_t(bh[nt], sb + offBh + b_off[nt] + ks * (16 * BST * 2));
                ldsm_x4_t(bl[nt], sb + offBl + b_off[nt] + ks * (16 * BST * 2));
            }
            #pragma unroll
            for (int mt = 0; mt < 4; mt++) {
                #pragma unroll
                for (int n8 = 0; n8 < 4; n8++) {
                    const uint32_t* ph = &bh[n8 >> 1][(n8 & 1) * 2];
                    const uint32_t* pl = &bl[n8 >> 1][(n8 & 1) * 2];
                    mma16816(acc[mt][n8], ah[mt], ph);
                    mma16816(acc[mt][n8], ah[mt], pl);
                    mma16816(acc[mt][n8], al[mt], ph);
                }
            }
        }
    }

    // epilogue
    #pragma unroll
    for (int mt = 0; mt < 4; mt++) {
        int r0g = m0 + wm + mt * 16 + (lane >> 2);
        float mv0 = maskrow[r0g], mv1 = maskrow[r0g + 8];
        float* y0 = Y + (size_t)r0g * CCH;
        float* y1 = y0 + (size_t)8 * CCH;
        #pragma unroll
        for (int n8 = 0; n8 < 4; n8++) {
            int c0g = n0 + wn + n8 * 8 + (lane & 3) * 2;
            float b0 = bias[c0g], b1 = bias[c0g + 1];
            float2 v0, v1;
            v0.x = fmaxf(acc[mt][n8][0] + b0, 0.f) * mv0;
            v0.y = fmaxf(acc[mt][n8][1] + b1, 0.f) * mv0;
            v1.x = fmaxf(acc[mt][n8][2] + b0, 0.f) * mv1;
            v1.y = fmaxf(acc[mt][n8][3] + b1, 0.f) * mv1;
            *(float2*)(y0 + c0g) = v0;
            *(float2*)(y1 + c0g) = v1;
        }
    }
}

// ---------------------------------------------------------------------------
extern "C" void kernel_launch(void* const* d_in, const int* in_sizes, int n_in,
                              void* d_out, int out_size) {
    const float *feats[3] = {}, *masks[3] = {}, *offs[3] = {};
    const float *w[2] = {}, *bias[2] = {}, *ow[2] = {}, *ob[2] = {};
    int wi = 0, bi = 0, owi = 0, obi = 0;
    for (int i = 0; i < n_in; i++) {
        const float* p = (const float*)d_in[i];
        switch (in_sizes[i]) {
            case 8 * 512 * 2048: feats[0] = p; break;
            case 8 * 512 * 1024: feats[1] = p; break;
            case 8 * 512 * 512:  feats[2] = p; break;
            case 8 * 2048:       masks[0] = p; break;
            case 8 * 1024:       masks[1] = p; break;
            case 8 * 512:        masks[2] = p; break;
            case 8 * 3 * 2048:   offs[0] = p; break;
            case 8 * 3 * 1024:   offs[1] = p; break;
            case 8 * 3 * 512:    offs[2] = p; break;
            case 512 * 512 * 3:  if (wi < 2)  w[wi++] = p; break;
            case 512:            if (bi < 2)  bias[bi++] = p; break;
            case 3 * 512 * 3:    if (owi < 2) ow[owi++] = p; break;
            case 3:              if (obi < 2) ob[obi++] = p; break;
            default: break;
        }
    }

    float *xb, *yb, *offa, *offb, *mrow;
    __nv_bfloat16 *Ah, *Al, *Wh, *Wl;
    cudaGetSymbolAddress((void**)&xb, g_x);
    cudaGetSymbolAddress((void**)&yb, g_y);
    cudaGetSymbolAddress((void**)&offa, g_offa);
    cudaGetSymbolAddress((void**)&offb, g_offb);
    cudaGetSymbolAddress((void**)&mrow, g_mrow);
    cudaGetSymbolAddress((void**)&Ah, g_Ah);
    cudaGetSymbolAddress((void**)&Al, g_Al);
    cudaGetSymbolAddress((void**)&Wh, g_Wh);
    cudaGetSymbolAddress((void**)&Wl, g_Wl);
    float* out = (float*)d_out;

    cudaFuncSetAttribute(gemm_mma_kernel,
                         cudaFuncAttributeMaxDynamicSharedMemorySize, GEMM_SMEM);

    {
        int total = 2 * KRED * CCH;
        prep_wsplit_kernel<<<(total + 255) / 256, 256>>>(w[0], w[1], Wh, Wl);
        maskrow_kernel<<<(ROWS_TOTAL + 255) / 256, 256>>>(masks[0], masks[1],
                                                          masks[2], mrow);
    }

    const int Ts[3]    = {2048, 1024, 512};
    const int lbase[3] = {0, LV0, LV01};

    for (int lv = 0; lv < 3; lv++) {
        int T = Ts[lv];
        transpose_kernel<<<dim3(T / 32, CCH / 32, BSZ), dim3(32, 8)>>>(
            feats[lv], xb + (size_t)lbase[lv] * CCH, CCH, T);
    }

    // ---- layer 0 ----
    for (int lv = 0; lv < 3; lv++)
        offset_kernel<true><<<Ts[lv], 256>>>(xb + (size_t)lbase[lv] * CCH, offs[lv],
                                             ow[0], ob[0], offa, Ts[lv], lbase[lv]);
    im2col_split_kernel<<<dim3(ROWS_TOTAL, KT), 128>>>(xb, offa, Ah, Al);
    gemm_mma_kernel<<<dim3(4, ROWS_TOTAL / BMM), 256, GEMM_SMEM>>>(
        Ah, Al, Wh, Wl, bias[0], mrow, yb);

    // ---- layer 1 ----
    for (int lv = 0; lv < 3; lv++)
        offset_kernel<false><<<Ts[lv], 256>>>(yb + (size_t)lbase[lv] * CCH, offa,
                                              ow[1], ob[1], offb, Ts[lv], lbase[lv]);
    im2col_split_kernel<<<dim3(ROWS_TOTAL, KT), 128>>>(yb, offb, Ah, Al);
    gemm_mma_kernel<<<dim3(4, ROWS_TOTAL / BMM), 256, GEMM_SMEM>>>(
        Ah, Al, Wh + (size_t)KRED * CCH, Wl + (size_t)KRED * CCH,
        bias[1], mrow, xb);

    // outputs
    size_t outBase[3] = {0, (size_t)BSZ * CCH * 2048,
                         (size_t)BSZ * CCH * (2048 + 1024)};
    size_t mb0 = (size_t)BSZ * CCH * 3584;
    size_t maskBase[3] = {mb0, mb0 + (size_t)BSZ * 2048, mb0 + (size_t)BSZ * 3072};
    for (int lv = 0; lv < 3; lv++) {
        int T = Ts[lv];
        transpose_kernel<<<dim3(CCH / 32, T / 32, BSZ), dim3(32, 8)>>>(
            xb + (size_t)lbase[lv] * CCH, out + outBase[lv], T, CCH);
        int nm = BSZ * T;
        maskout_kernel<<<(nm + 255) / 256, 256>>>(masks[lv], out + maskBase[lv], nm);
    }
}

// round 5
// speedup vs baseline: 2.5657x; 1.0065x over previous
#include <cuda_runtime.h>
#include <cuda_bf16.h>
#include <cstdint>

// ---------------------------------------------------------------------------
// FeatureAlign via mma.sync bf16 (HMMA) with fp32->bf16 hi/lo splitting.
//   Y = relu( A(fp32 gathered) @ W(fp32) + b ) * mask
//   A@W ~= Ah@Wh + Ah@Wl + Al@Wh   (fp32 accum)
// im2col gather is FUSED into the GEMM A-producer (table-driven, per CTA).
// All 3 pyramid levels concatenated into 28672 rows; one GEMM per layer.
// ---------------------------------------------------------------------------

#define BSZ 8
#define CCH 512
#define KT  3
#define ROWS_TOTAL 28672
#define LV0 16384
#define LV01 24576
#define KRED 1536

// GEMM tiling
#define BMM 128
#define BNN 128
#define BKK 32
#define AST 40                       // A smem row stride (bf16): 32 + 8 pad
#define BST 136                      // B smem row stride: 128 + 8 pad
#define KITERS (KRED/BKK)            // 48

// SMEM layout (bytes)
#define A_HI   10240u                // 128*40*2
#define ABUF   20480u                // hi+lo
#define B_OFF  40960u                // after 2 A buffers
#define B_STG  17408u                // (hi+lo) 32*136*2*2
#define TBL    93184u                // after 3 B stages
#define GEMM_SMEM 101376             // TBL + 4*512*4

// scratch (device globals; no runtime allocation allowed)
__device__ float g_x[ROWS_TOTAL * CCH];
__device__ float g_y[ROWS_TOTAL * CCH];
__device__ float g_offa[ROWS_TOTAL * 4];
__device__ float g_offb[ROWS_TOTAL * 4];
__device__ float g_mrow[ROWS_TOTAL];
__device__ __nv_bfloat16 g_Wh[2 * KRED * CCH];
__device__ __nv_bfloat16 g_Wl[2 * KRED * CCH];

// ---------------------------------------------------------------------------
__device__ __forceinline__ uint32_t smem_u32(const void* p) {
    return (uint32_t)__cvta_generic_to_shared(p);
}
#define CP16(sa, gp) \
    asm volatile("cp.async.cg.shared.global [%0], [%1], 16;" :: "r"(sa), "l"(gp))
#define CP_COMMIT() asm volatile("cp.async.commit_group;")
#define CP_WAIT1()  asm volatile("cp.async.wait_group 1;")

__device__ __forceinline__ void ldsm_x4(uint32_t* r, uint32_t a) {
    asm volatile("ldmatrix.sync.aligned.m8n8.x4.shared.b16 {%0,%1,%2,%3}, [%4];"
                 : "=r"(r[0]), "=r"(r[1]), "=r"(r[2]), "=r"(r[3]) : "r"(a));
}
__device__ __forceinline__ void ldsm_x4_t(uint32_t* r, uint32_t a) {
    asm volatile("ldmatrix.sync.aligned.m8n8.x4.trans.shared.b16 {%0,%1,%2,%3}, [%4];"
                 : "=r"(r[0]), "=r"(r[1]), "=r"(r[2]), "=r"(r[3]) : "r"(a));
}
__device__ __forceinline__ void mma16816(float* d, const uint32_t* a,
                                         const uint32_t* b) {
    asm volatile("mma.sync.aligned.m16n8k16.row.col.f32.bf16.bf16.f32 "
                 "{%0,%1,%2,%3}, {%4,%5,%6,%7}, {%8,%9}, {%0,%1,%2,%3};"
                 : "+f"(d[0]), "+f"(d[1]), "+f"(d[2]), "+f"(d[3])
                 : "r"(a[0]), "r"(a[1]), "r"(a[2]), "r"(a[3]), "r"(b[0]), "r"(b[1]));
}

// ---------------------------------------------------------------------------
// batched transpose: in (B, R, S) -> out (B, S, R)
__global__ void transpose_kernel(const float* __restrict__ in,
                                 float* __restrict__ out, int R, int S) {
    __shared__ float tile[32][33];
    int b = blockIdx.z, s0 = blockIdx.x * 32, r0 = blockIdx.y * 32;
    const float* inb = in + (size_t)b * R * S;
    float* outb = out + (size_t)b * R * S;
    #pragma unroll
    for (int i = threadIdx.y; i < 32; i += 8)
        tile[i][threadIdx.x] = inb[(size_t)(r0 + i) * S + s0 + threadIdx.x];
    __syncthreads();
    #pragma unroll
    for (int i = threadIdx.y; i < 32; i += 8)
        outb[(size_t)(s0 + i) * R + r0 + threadIdx.x] = tile[threadIdx.x][i];
}

// ---------------------------------------------------------------------------
// Wh/Wl[l][k][n], k = ktap*512 + c ; from w[(n*512 + c)*3 + ktap]
__global__ void prep_wsplit_kernel(const float* __restrict__ w0,
                                   const float* __restrict__ w1,
                                   __nv_bfloat16* __restrict__ Wh,
                                   __nv_bfloat16* __restrict__ Wl) {
    int idx = blockIdx.x * blockDim.x + threadIdx.x;
    if (idx >= 2 * KRED * CCH) return;
    int n = idx & 511;
    int k = (idx >> 9) % KRED;
    int l = idx / (KRED * CCH);
    int ktap = k >> 9, c = k & 511;
    const float* w = l ? w1 : w0;
    float val = w[(n * CCH + c) * KT + ktap];
    __nv_bfloat16 hi = __float2bfloat16(val);
    Wh[idx] = hi;
    Wl[idx] = __float2bfloat16(val - __bfloat162float(hi));
}

// ---------------------------------------------------------------------------
__global__ void maskrow_kernel(const float* __restrict__ m0,
                               const float* __restrict__ m1,
                               const float* __restrict__ m2,
                               float* __restrict__ out) {
    int m = blockIdx.x * 256 + threadIdx.x;
    if (m >= ROWS_TOTAL) return;
    out[m] = (m < LV0) ? m0[m] : (m < LV01 ? m1[m - LV0] : m2[m - LV01]);
}
__global__ void maskout_kernel(const float* __restrict__ in,
                               float* __restrict__ out, int n) {
    int i = blockIdx.x * blockDim.x + threadIdx.x;
    if (i < n) out[i] = (in[i] != 0.f) ? 1.0f : 0.0f;
}

// ---------------------------------------------------------------------------
// offset conv: one warp per (b,t). X = this level's rows (row-major C).
template <bool EXT>
__global__ void offset_kernel(const float* __restrict__ X,
                              const float* __restrict__ off_in,
                              const float* __restrict__ ow,
                              const float* __restrict__ ob,
                              float* __restrict__ off_out,  // [m*4+k] absolute
                              int T, int lbase) {
    __shared__ float ow_sh[KT * CCH * KT];
    for (int i = threadIdx.x; i < KT * CCH * KT; i += blockDim.x)
        ow_sh[i] = ow[i];
    __syncthreads();

    int warp = threadIdx.x >> 5, lane = threadIdx.x & 31;
    int rl = blockIdx.x * 8 + warp;
    int b = rl / T, t = rl % T;
    int m = lbase + rl;

    const float* x0 = X + (size_t)rl * CCH;
    const float* xm = (t > 0)     ? x0 - CCH : nullptr;
    const float* xp = (t < T - 1) ? x0 + CCH : nullptr;

    float a0 = 0.f, a1 = 0.f, a2 = 0.f;
    for (int c = lane; c < CCH; c += 32) {
        float vm = xm ? xm[c] : 0.f;
        float v0 = x0[c];
        float vp = xp ? xp[c] : 0.f;
        const float* o0 = &ow_sh[c * KT];
        const float* o1 = &ow_sh[(CCH + c) * KT];
        const float* o2 = &ow_sh[(2 * CCH + c) * KT];
        a0 += o0[0] * vm + o0[1] * v0 + o0[2] * vp;
        a1 += o1[0] * vm + o1[1] * v0 + o1[2] * vp;
        a2 += o2[0] * vm + o2[1] * v0 + o2[2] * vp;
    }
    #pragma unroll
    for (int s = 16; s; s >>= 1) {
        a0 += __shfl_down_sync(0xffffffffu, a0, s);
        a1 += __shfl_down_sync(0xffffffffu, a1, s);
        a2 += __shfl_down_sync(0xffffffffu, a2, s);
    }
    if (lane == 0) {
        float i0, i1, i2;
        if (EXT) {
            i0 = off_in[((size_t)b * KT + 0) * T + t];
            i1 = off_in[((size_t)b * KT + 1) * T + t];
            i2 = off_in[((size_t)b * KT + 2) * T + t];
        } else {
            i0 = off_in[(size_t)m * 4 + 0];
            i1 = off_in[(size_t)m * 4 + 1];
            i2 = off_in[(size_t)m * 4 + 2];
        }
        off_out[(size_t)m * 4 + 0] = a0 + ob[0] + i0;
        off_out[(size_t)m * 4 + 1] = a1 + ob[1] + i1;
        off_out[(size_t)m * 4 + 2] = a2 + ob[2] + i2;
    }
}

// ---------------------------------------------------------------------------
// Fused gather+GEMM: Y[m,n] = relu((A@W)[m,n] + bias[n]) * maskrow[m]
// A[m, tap*512+c] = lerp of X rows (table-driven), split to bf16 hi/lo in smem.
// grid (4, 224), 256 threads.
__global__ __launch_bounds__(256, 1)
void gemm_fused_kernel(const float* __restrict__ X,
                       const float* __restrict__ OFF,
                       const __nv_bfloat16* __restrict__ Whg,
                       const __nv_bfloat16* __restrict__ Wlg,
                       const float* __restrict__ bias,
                       const float* __restrict__ maskrow,
                       float* __restrict__ Y) {
    extern __shared__ char sm[];
    uint32_t sbase = smem_u32(sm);
    int tid = threadIdx.x, warp = tid >> 5, lane = tid & 31;
    int m0 = blockIdx.y * BMM, n0 = blockIdx.x * BNN;

    int* ir0s = (int*)(sm + TBL);
    int* ir1s = (int*)(sm + TBL + 2048);
    float* fw0s = (float*)(sm + TBL + 4096);
    float* fw1s = (float*)(sm + TBL + 6144);

    // level geometry (whole 128-row block is inside one level)
    int lv = (m0 < LV0) ? 0 : (m0 < LV01 ? 1 : 2);
    int lbase = (lv == 0) ? 0 : (lv == 1 ? LV0 : LV01);
    int logT = 11 - lv;
    int T = 1 << logT;

    // build gather tables: (row r, tap kk) -> abs rows + lerp weights
    for (int idx = tid; idx < 512; idx += 256) {
        int r = idx >> 2, kk = idx & 3;
        int m = m0 + r;
        int rl = m - lbase;
        int b = rl >> logT, t = rl & (T - 1);
        float off = (kk < 3) ? OFF[(size_t)m * 4 + kk] : 0.f;
        float pos = (float)(t + kk - 1) + off;
        float p0f = floorf(pos);
        float f = pos - p0f;
        int i0 = (int)p0f, i1 = i0 + 1;
        float w0 = (i0 >= 0 && i0 < T) ? (1.0f - f) : 0.0f;
        float w1 = (i1 >= 0 && i1 < T) ? f : 0.0f;
        int i0c = min(max(i0, 0), T - 1);
        int i1c = min(max(i1, 0), T - 1);
        int base = lbase + (b << logT);
        ir0s[idx] = base + i0c;
        ir1s[idx] = base + i1c;
        fw0s[idx] = w0;
        fw1s[idx] = w1;
    }
    __syncthreads();

    // B cp.async geometry
    int br0 = tid >> 4, bnc = (tid & 15) * 8;
    const __nv_bfloat16* gBh0 = Whg + (size_t)br0 * CCH + n0 + bnc;
    const __nv_bfloat16* gBh1 = Whg + (size_t)(br0 + 16) * CCH + n0 + bnc;
    const __nv_bfloat16* gBl0 = Wlg + (size_t)br0 * CCH + n0 + bnc;
    const __nv_bfloat16* gBl1 = Wlg + (size_t)(br0 + 16) * CCH + n0 + bnc;
    uint32_t sB0 = (uint32_t)(br0 * BST + bnc) * 2;
    uint32_t sB1 = (uint32_t)((br0 + 16) * BST + bnc) * 2;

    auto load_B = [&](int st, int k0) {
        uint32_t sb = sbase + B_OFF + (uint32_t)st * B_STG;
        CP16(sb + sB0, gBh0 + (size_t)k0 * CCH);
        CP16(sb + sB1, gBh1 + (size_t)k0 * CCH);
        CP16(sb + 8704u + sB0, gBl0 + (size_t)k0 * CCH);
        CP16(sb + 8704u + sB1, gBl1 + (size_t)k0 * CCH);
    };

    // A gather geometry: thread -> (row, 16-channel half)
    int ar = tid >> 1, ahc = tid & 1;
    uint32_t aDst = (uint32_t)(ar * AST + ahc * 16) * 2;   // bytes within hi buf

    float4 g[8];
    auto gatherA = [&](int cc) {
        int tap = cc >> 4;
        int c0 = (cc * 32) & 511;
        int tb = ar * 4 + tap;
        const float4* p0 = (const float4*)(X + (size_t)ir0s[tb] * CCH + c0 + ahc * 16);
        const float4* p1 = (const float4*)(X + (size_t)ir1s[tb] * CCH + c0 + ahc * 16);
        #pragma unroll
        for (int q = 0; q < 4; q++) { g[q] = p0[q]; g[q + 4] = p1[q]; }
    };
    auto storeA = [&](int cc, int buf) {
        int tap = cc >> 4;
        int tb = ar * 4 + tap;
        float w0 = fw0s[tb], w1 = fw1s[tb];
        uint32_t hv[8], lvv[8];
        #pragma unroll
        for (int q = 0; q < 4; q++) {
            float e0 = w0 * g[q].x + w1 * g[q + 4].x;
            float e1 = w0 * g[q].y + w1 * g[q + 4].y;
            float e2 = w0 * g[q].z + w1 * g[q + 4].z;
            float e3 = w0 * g[q].w + w1 * g[q + 4].w;
            __nv_bfloat162 h01 = __floats2bfloat162_rn(e0, e1);
            __nv_bfloat162 h23 = __floats2bfloat162_rn(e2, e3);
            float2 f01 = __bfloat1622float2(h01);
            float2 f23 = __bfloat1622float2(h23);
            __nv_bfloat162 l01 = __floats2bfloat162_rn(e0 - f01.x, e1 - f01.y);
            __nv_bfloat162 l23 = __floats2bfloat162_rn(e2 - f23.x, e3 - f23.y);
            hv[2 * q]     = *reinterpret_cast<uint32_t*>(&h01);
            hv[2 * q + 1] = *reinterpret_cast<uint32_t*>(&h23);
            lvv[2 * q]     = *reinterpret_cast<uint32_t*>(&l01);
            lvv[2 * q + 1] = *reinterpret_cast<uint32_t*>(&l23);
        }
        uint32_t d = sbase + (uint32_t)buf * ABUF + aDst;
        asm volatile("st.shared.v4.b32 [%0], {%1,%2,%3,%4};"
                     :: "r"(d), "r"(hv[0]), "r"(hv[1]), "r"(hv[2]), "r"(hv[3]));
        asm volatile("st.shared.v4.b32 [%0], {%1,%2,%3,%4};"
                     :: "r"(d + 16), "r"(hv[4]), "r"(hv[5]), "r"(hv[6]), "r"(hv[7]));
        asm volatile("st.shared.v4.b32 [%0], {%1,%2,%3,%4};"
                     :: "r"(d + A_HI), "r"(lvv[0]), "r"(lvv[1]), "r"(lvv[2]), "r"(lvv[3]));
        asm volatile("st.shared.v4.b32 [%0], {%1,%2,%3,%4};"
                     :: "r"(d + A_HI + 16), "r"(lvv[4]), "r"(lvv[5]), "r"(lvv[6]), "r"(lvv[7]));
    };

    // ldmatrix per-thread offsets
    int wm = (warp >> 2) * 64, wn = (warp & 3) * 32;
    int lr = lane & 15, lc = lane >> 4;
    uint32_t a_off[4], b_off[2];
    #pragma unroll
    for (int mt = 0; mt < 4; mt++)
        a_off[mt] = (uint32_t)((wm + mt * 16 + lr) * AST + lc * 8) * 2;
    #pragma unroll
    for (int nt = 0; nt < 2; nt++)
        b_off[nt] = (uint32_t)(lr * BST + wn + nt * 16 + lc * 8) * 2;

    float acc[4][4][4];
    #pragma unroll
    for (int i = 0; i < 4; i++)
        #pragma unroll
        for (int j = 0; j < 4; j++)
            #pragma unroll
            for (int q = 0; q < 4; q++) acc[i][j][q] = 0.f;

    // prologue: B stages 0,1 in flight; A chunk 0 in buffer 0
    load_B(0, 0); CP_COMMIT();
    load_B(1, BKK); CP_COMMIT();
    gatherA(0);
    storeA(0, 0);

    for (int it = 0; it < KITERS; it++) {
        CP_WAIT1();
        __syncthreads();                 // B(it) + A(it) visible
        if (it + 2 < KITERS) load_B((it + 2) % 3, (it + 2) * BKK);
        CP_COMMIT();
        if (it + 1 < KITERS) gatherA(it + 1);   // LDGs issued under MMAs

        uint32_t ab = sbase + (uint32_t)(it & 1) * ABUF;
        uint32_t bb = sbase + B_OFF + (uint32_t)(it % 3) * B_STG;
        #pragma unroll
        for (int ks = 0; ks < 2; ks++) {
            uint32_t ah[4][4], al[4][4], bh[2][4], bl[2][4];
            #pragma unroll
            for (int mt = 0; mt < 4; mt++) {
                ldsm_x4(ah[mt], ab + a_off[mt] + ks * 32);
                ldsm_x4(al[mt], ab + A_HI + a_off[mt] + ks * 32);
            }
            #pragma unroll
            for (int nt = 0; nt < 2; nt++) {
                ldsm_x4_t(bh[nt], bb + b_off[nt] + ks * (16 * BST * 2));
                ldsm_x4_t(bl[nt], bb + 8704u + b_off[nt] + ks * (16 * BST * 2));
            }
            #pragma unroll
            for (int mt = 0; mt < 4; mt++) {
                #pragma unroll
                for (int n8 = 0; n8 < 4; n8++) {
                    const uint32_t* ph = &bh[n8 >> 1][(n8 & 1) * 2];
                    const uint32_t* pl = &bl[n8 >> 1][(n8 & 1) * 2];
                    mma16816(acc[mt][n8], ah[mt], ph);
                    mma16816(acc[mt][n8], ah[mt], pl);
                    mma16816(acc[mt][n8], al[mt], ph);
                }
            }
        }
        if (it + 1 < KITERS) storeA(it + 1, (it + 1) & 1);
    }

    // epilogue
    #pragma unroll
    for (int mt = 0; mt < 4; mt++) {
        int r0g = m0 + wm + mt * 16 + (lane >> 2);
        float mv0 = maskrow[r0g], mv1 = maskrow[r0g + 8];
        float* y0 = Y + (size_t)r0g * CCH;
        float* y1 = y0 + (size_t)8 * CCH;
        #pragma unroll
        for (int n8 = 0; n8 < 4; n8++) {
            int c0g = n0 + wn + n8 * 8 + (lane & 3) * 2;
            float b0 = bias[c0g], b1 = bias[c0g + 1];
            float2 v0, v1;
            v0.x = fmaxf(acc[mt][n8][0] + b0, 0.f) * mv0;
            v0.y = fmaxf(acc[mt][n8][1] + b1, 0.f) * mv0;
            v1.x = fmaxf(acc[mt][n8][2] + b0, 0.f) * mv1;
            v1.y = fmaxf(acc[mt][n8][3] + b1, 0.f) * mv1;
            *(float2*)(y0 + c0g) = v0;
            *(float2*)(y1 + c0g) = v1;
        }
    }
}

// ---------------------------------------------------------------------------
extern "C" void kernel_launch(void* const* d_in, const int* in_sizes, int n_in,
                              void* d_out, int out_size) {
    const float *feats[3] = {}, *masks[3] = {}, *offs[3] = {};
    const float *w[2] = {}, *bias[2] = {}, *ow[2] = {}, *ob[2] = {};
    int wi = 0, bi = 0, owi = 0, obi = 0;
    for (int i = 0; i < n_in; i++) {
        const float* p = (const float*)d_in[i];
        switch (in_sizes[i]) {
            case 8 * 512 * 2048: feats[0] = p; break;
            case 8 * 512 * 1024: feats[1] = p; break;
            case 8 * 512 * 512:  feats[2] = p; break;
            case 8 * 2048:       masks[0] = p; break;
            case 8 * 1024:       masks[1] = p; break;
            case 8 * 512:        masks[2] = p; break;
            case 8 * 3 * 2048:   offs[0] = p; break;
            case 8 * 3 * 1024:   offs[1] = p; break;
            case 8 * 3 * 512:    offs[2] = p; break;
            case 512 * 512 * 3:  if (wi < 2)  w[wi++] = p; break;
            case 512:            if (bi < 2)  bias[bi++] = p; break;
            case 3 * 512 * 3:    if (owi < 2) ow[owi++] = p; break;
            case 3:              if (obi < 2) ob[obi++] = p; break;
            default: break;
        }
    }

    float *xb, *yb, *offa, *offb, *mrow;
    __nv_bfloat16 *Wh, *Wl;
    cudaGetSymbolAddress((void**)&xb, g_x);
    cudaGetSymbolAddress((void**)&yb, g_y);
    cudaGetSymbolAddress((void**)&offa, g_offa);
    cudaGetSymbolAddress((void**)&offb, g_offb);
    cudaGetSymbolAddress((void**)&mrow, g_mrow);
    cudaGetSymbolAddress((void**)&Wh, g_Wh);
    cudaGetSymbolAddress((void**)&Wl, g_Wl);
    float* out = (float*)d_out;

    cudaFuncSetAttribute(gemm_fused_kernel,
                         cudaFuncAttributeMaxDynamicSharedMemorySize, GEMM_SMEM);

    {
        int total = 2 * KRED * CCH;
        prep_wsplit_kernel<<<(total + 255) / 256, 256>>>(w[0], w[1], Wh, Wl);
        maskrow_kernel<<<(ROWS_TOTAL + 255) / 256, 256>>>(masks[0], masks[1],
                                                          masks[2], mrow);
    }

    const int Ts[3]    = {2048, 1024, 512};
    const int lbase[3] = {0, LV0, LV01};

    for (int lv = 0; lv < 3; lv++) {
        int T = Ts[lv];
        transpose_kernel<<<dim3(T / 32, CCH / 32, BSZ), dim3(32, 8)>>>(
            feats[lv], xb + (size_t)lbase[lv] * CCH, CCH, T);
    }

    // ---- layer 0 ----
    for (int lv = 0; lv < 3; lv++)
        offset_kernel<true><<<Ts[lv], 256>>>(xb + (size_t)lbase[lv] * CCH, offs[lv],
                                             ow[0], ob[0], offa, Ts[lv], lbase[lv]);
    gemm_fused_kernel<<<dim3(4, ROWS_TOTAL / BMM), 256, GEMM_SMEM>>>(
        xb, offa, Wh, Wl, bias[0], mrow, yb);

    // ---- layer 1 ----
    for (int lv = 0; lv < 3; lv++)
        offset_kernel<false><<<Ts[lv], 256>>>(yb + (size_t)lbase[lv] * CCH, offa,
                                              ow[1], ob[1], offb, Ts[lv], lbase[lv]);
    gemm_fused_kernel<<<dim3(4, ROWS_TOTAL / BMM), 256, GEMM_SMEM>>>(
        yb, offb, Wh + (size_t)KRED * CCH, Wl + (size_t)KRED * CCH,
        bias[1], mrow, xb);

    // outputs
    size_t outBase[3] = {0, (size_t)BSZ * CCH * 2048,
                         (size_t)BSZ * CCH * (2048 + 1024)};
    size_t mb0 = (size_t)BSZ * CCH * 3584;
    size_t maskBase[3] = {mb0, mb0 + (size_t)BSZ * 2048, mb0 + (size_t)BSZ * 3072};
    for (int lv = 0; lv < 3; lv++) {
        int T = Ts[lv];
        transpose_kernel<<<dim3(CCH / 32, T / 32, BSZ), dim3(32, 8)>>>(
            xb + (size_t)lbase[lv] * CCH, out + outBase[lv], T, CCH);
        int nm = BSZ * T;
        maskout_kernel<<<(nm + 255) / 256, 256>>>(masks[lv], out + maskBase[lv], nm);
    }
}